// round 11
// baseline (speedup 1.0000x reference)
#include <cuda_runtime.h>
#include <cuda_bf16.h>
#include <cstdint>
#include <math.h>

#define TT   4096
#define CC   1024
#define HH   16
#define DD   64
#define WIN  1024
#define SCALE_F 0.12f

// scratch (allocation-free contract: __device__ globals)
__device__ float    g_qkv[TT * 3 * CC];     // fp32 qkv projection output
__device__ uint32_t g_q[HH * TT * DD];      // tf32 bit patterns
__device__ uint32_t g_k[HH * TT * DD];
__device__ uint32_t g_v[HH * TT * DD];
__device__ uint32_t g_att[TT * CC];         // tf32 attention output
__device__ uint32_t g_xt[TT * CC];          // tf32 x
__device__ uint32_t g_wqkvt[3 * CC * CC];   // tf32 w_qkv
__device__ uint32_t g_wot[CC * CC];         // tf32 w_o

__device__ __forceinline__ uint32_t f2tf(float f) {
    uint32_t u;
    asm("cvt.rn.tf32.f32 %0, %1;" : "=r"(u) : "f"(f));
    return u;
}

__device__ __forceinline__ void mma_tf32_16n8k8(float* c, const uint32_t* a,
                                                const uint32_t* b) {
    asm volatile(
        "mma.sync.aligned.m16n8k8.row.col.f32.tf32.tf32.f32 "
        "{%0,%1,%2,%3}, {%4,%5,%6,%7}, {%8,%9}, {%0,%1,%2,%3};"
        : "+f"(c[0]), "+f"(c[1]), "+f"(c[2]), "+f"(c[3])
        : "r"(a[0]), "r"(a[1]), "r"(a[2]), "r"(a[3]), "r"(b[0]), "r"(b[1]));
}

__device__ __forceinline__ void cpasync16(uint32_t saddr, const void* g) {
    asm volatile("cp.async.cg.shared.global [%0], [%1], 16;"
                 :: "r"(saddr), "l"(g) : "memory");
}
#define CP_COMMIT() asm volatile("cp.async.commit_group;" ::: "memory")
#define CP_WAIT0()  asm volatile("cp.async.wait_group 0;" ::: "memory")
#define CP_WAIT1()  asm volatile("cp.async.wait_group 1;" ::: "memory")

// ---------------------------------------------------------------------------
// fp32 -> tf32 bulk convert
// ---------------------------------------------------------------------------
__global__ void cvt_tf32_k(const float4* __restrict__ in, uint4* __restrict__ out,
                           int n4)
{
    int i = blockIdx.x * 256 + threadIdx.x;
    if (i < n4) {
        float4 v = in[i];
        out[i] = make_uint4(f2tf(v.x), f2tf(v.y), f2tf(v.z), f2tf(v.w));
    }
}

// ===========================================================================
// C[M,N] = A[M,K] * B[N,K]^T, A/B already tf32 in global.
// 3-stage cp.async pipeline + register double-buffered fragments.
// 128x128 CTA tile, K-chunk 32, 256 thr / 8 warps (warp tile 32x64).
// ===========================================================================
#define SSTR  36
#define CHUNK (128 * SSTR)            // u32 per operand per stage
#define GSTAGE (2 * CHUNK)            // A+B per stage
#define GSMEM_B (3 * GSTAGE * 4)      // 110592 bytes

__global__ __launch_bounds__(256, 2)
void gemm_mma(const uint32_t* __restrict__ A, const uint32_t* __restrict__ B,
              float* __restrict__ C, int M, int N, int K)
{
    extern __shared__ uint32_t smg[];   // [3 stages][A CHUNK | B CHUNK]

    const int tid = threadIdx.x;
    const int wid = tid >> 5, lid = tid & 31;
    const int g = lid >> 2, t = lid & 3;
    const int wm = wid >> 1, wn = wid & 1;
    const int bm = blockIdx.y * 128, bn = blockIdx.x * 128;

    const int srow = tid >> 3, sc4 = (tid & 7) * 4;

    float acc[2][8][4];
    #pragma unroll
    for (int i = 0; i < 2; i++)
        #pragma unroll
        for (int j = 0; j < 8; j++)
            #pragma unroll
            for (int l = 0; l < 4; l++) acc[i][j][l] = 0.f;

    const uint32_t* Agb = A + (size_t)bm * K;
    const uint32_t* Bgb = B + (size_t)bn * K;
    const uint32_t smem0 = (uint32_t)__cvta_generic_to_shared(smg);

    // prologue: issue chunks 0,1 into stages 0,1
    #pragma unroll
    for (int p = 0; p < 2; p++) {
        uint32_t sA = smem0 + p * GSTAGE * 4;
        uint32_t sB = sA + CHUNK * 4;
        const uint32_t* Ag = Agb + p * 32;
        const uint32_t* Bg = Bgb + p * 32;
        #pragma unroll
        for (int i = 0; i < 4; i++) {
            int row = srow + i * 32;
            uint32_t so = (uint32_t)(row * SSTR + sc4) * 4;
            cpasync16(sA + so, Ag + (size_t)row * K + sc4);
            cpasync16(sB + so, Bg + (size_t)row * K + sc4);
        }
        CP_COMMIT();
    }

    const int nc = K / 32;   // >= 2
    int stage = 0;
    for (int c = 0; c < nc; c++) {
        if (c + 1 < nc) CP_WAIT1(); else CP_WAIT0();   // chunk c resident
        __syncthreads();   // visible to all; all warps done with stage being reused

        if (c + 2 < nc) {  // issue chunk c+2 into stage (c+2)%3
            int ns = stage + 2; if (ns >= 3) ns -= 3;
            uint32_t sA = smem0 + ns * GSTAGE * 4;
            uint32_t sB = sA + CHUNK * 4;
            const uint32_t* Ag = Agb + (c + 2) * 32;
            const uint32_t* Bg = Bgb + (c + 2) * 32;
            #pragma unroll
            for (int i = 0; i < 4; i++) {
                int row = srow + i * 32;
                uint32_t so = (uint32_t)(row * SSTR + sc4) * 4;
                cpasync16(sA + so, Ag + (size_t)row * K + sc4);
                cpasync16(sB + so, Bg + (size_t)row * K + sc4);
            }
            CP_COMMIT();
        }

        const uint32_t* As = smg + stage * GSTAGE;
        const uint32_t* Bs = As + CHUNK;

        // register double-buffered fragments over the 4 k-steps
        uint32_t af[2][2][4], bf[2][8][2];
        {
            const int kb = 0;
            #pragma unroll
            for (int mt = 0; mt < 2; mt++) {
                int r0 = wm * 32 + mt * 16 + g;
                af[0][mt][0] = As[(r0    ) * SSTR + kb + t];
                af[0][mt][1] = As[(r0 + 8) * SSTR + kb + t];
                af[0][mt][2] = As[(r0    ) * SSTR + kb + t + 4];
                af[0][mt][3] = As[(r0 + 8) * SSTR + kb + t + 4];
            }
            #pragma unroll
            for (int nt = 0; nt < 8; nt++) {
                int n0 = wn * 64 + nt * 8 + g;
                bf[0][nt][0] = Bs[n0 * SSTR + kb + t];
                bf[0][nt][1] = Bs[n0 * SSTR + kb + t + 4];
            }
        }
        #pragma unroll
        for (int ks = 0; ks < 4; ks++) {
            const int cur = ks & 1, nxt = cur ^ 1;
            if (ks < 3) {
                const int kb = (ks + 1) * 8;
                #pragma unroll
                for (int mt = 0; mt < 2; mt++) {
                    int r0 = wm * 32 + mt * 16 + g;
                    af[nxt][mt][0] = As[(r0    ) * SSTR + kb + t];
                    af[nxt][mt][1] = As[(r0 + 8) * SSTR + kb + t];
                    af[nxt][mt][2] = As[(r0    ) * SSTR + kb + t + 4];
                    af[nxt][mt][3] = As[(r0 + 8) * SSTR + kb + t + 4];
                }
                #pragma unroll
                for (int nt = 0; nt < 8; nt++) {
                    int n0 = wn * 64 + nt * 8 + g;
                    bf[nxt][nt][0] = Bs[n0 * SSTR + kb + t];
                    bf[nxt][nt][1] = Bs[n0 * SSTR + kb + t + 4];
                }
            }
            #pragma unroll
            for (int mt = 0; mt < 2; mt++)
                #pragma unroll
                for (int nt = 0; nt < 8; nt++)
                    mma_tf32_16n8k8(acc[mt][nt], af[cur][mt], bf[cur][nt]);
        }
        stage++; if (stage >= 3) stage = 0;
    }

    #pragma unroll
    for (int mt = 0; mt < 2; mt++) {
        int row0 = bm + wm * 32 + mt * 16 + g;
        #pragma unroll
        for (int nt = 0; nt < 8; nt++) {
            int col = bn + wn * 64 + nt * 8 + 2 * t;
            *(float2*)(C + (size_t)row0 * N + col) =
                make_float2(acc[mt][nt][0], acc[mt][nt][1]);
            *(float2*)(C + (size_t)(row0 + 8) * N + col) =
                make_float2(acc[mt][nt][2], acc[mt][nt][3]);
        }
    }
}

// ---------------------------------------------------------------------------
// Split qkv row into per-head Q/K/V with RMSNorm + RoPE (Q,K) and 0.5*V.
// Outputs stored as tf32 bit patterns.
// ---------------------------------------------------------------------------
__global__ void qkv_post(const float* __restrict__ cosT, const float* __restrict__ sinT,
                         const float* __restrict__ qw, const float* __restrict__ kw)
{
    const int t    = blockIdx.x;
    const int h    = threadIdx.x >> 5;
    const int lane = threadIdx.x & 31;
    const int d0   = lane * 2;
    const float* row = g_qkv + (size_t)t * (3 * CC);

    float cv = 0.f, sv = 0.f;
    if (lane < 16) { cv = cosT[t * 16 + lane]; sv = sinT[t * 16 + lane]; }

    float2 q2 = *(const float2*)(row + h * 64 + d0);
    float ss = q2.x * q2.x + q2.y * q2.y;
    #pragma unroll
    for (int off = 16; off; off >>= 1) ss += __shfl_xor_sync(0xffffffffu, ss, off);
    float rn = rsqrtf(ss * (1.f / 64.f) + 1e-6f);
    float qa = q2.x * rn * qw[d0];
    float qb = q2.y * rn * qw[d0 + 1];
    if (lane < 16) {
        float e = qa, od = qb;
        qa = e * cv - od * sv;
        qb = e * sv + od * cv;
    }
    *(uint2*)(g_q + ((size_t)h * TT + t) * 64 + d0) = make_uint2(f2tf(qa), f2tf(qb));

    float2 k2 = *(const float2*)(row + CC + h * 64 + d0);
    float ssk = k2.x * k2.x + k2.y * k2.y;
    #pragma unroll
    for (int off = 16; off; off >>= 1) ssk += __shfl_xor_sync(0xffffffffu, ssk, off);
    float rk = rsqrtf(ssk * (1.f / 64.f) + 1e-6f);
    float ka = k2.x * rk * kw[d0];
    float kb = k2.y * rk * kw[d0 + 1];
    if (lane < 16) {
        float e = ka, od = kb;
        ka = e * cv - od * sv;
        kb = e * sv + od * cv;
    }
    *(uint2*)(g_k + ((size_t)h * TT + t) * 64 + d0) = make_uint2(f2tf(ka), f2tf(kb));

    float2 v2 = *(const float2*)(row + 2 * CC + h * 64 + d0);
    *(uint2*)(g_v + ((size_t)h * TT + t) * 64 + d0) =
        make_uint2(f2tf(v2.x * 0.5f), f2tf(v2.y * 0.5f));
}

// ===========================================================================
// Sliding-window flash attention on tensor pipe (mma.sync tf32).
// cp.async double-buffered K/V. 128 queries x 1 head per CTA, 8 warps.
// ===========================================================================
#define QSTR 68
#define VSTR 72
#define KV_WORDS (64 * QSTR + 64 * VSTR)
#define ATT_SMEM ((128 * QSTR + 128 * QSTR + 2 * KV_WORDS) * 4)

__global__ __launch_bounds__(256, 1)
void attn_mma()
{
    extern __shared__ uint32_t sm4[];
    uint32_t* Qs  = sm4;                    // [128][68]
    uint32_t* Ps  = Qs + 128 * QSTR;        // [128][68]
    uint32_t* KV0 = Ps + 128 * QSTR;        // [2][ Ks 64x68 | Vs 64x72 ]

    const int h  = blockIdx.y;
    const int qb = blockIdx.x;
    const int t0 = qb * 128;
    const int tid = threadIdx.x;
    const int wid = tid >> 5, lid = tid & 31;
    const int g = lid >> 2, t = lid & 3;
    const int r0 = wid * 16;

    const uint32_t* Qg = g_q + ((size_t)h * TT + t0) * 64;
    const uint32_t* Kg = g_k + (size_t)h * TT * 64;
    const uint32_t* Vg = g_v + (size_t)h * TT * 64;
    const uint32_t kv_s0 = (uint32_t)__cvta_generic_to_shared(KV0);

    int jb_lo = 2 * qb - 16; if (jb_lo < 0) jb_lo = 0;
    const int jb_hi = 2 * qb + 1;

    // prologue: issue K/V for first block into buffer 0
    {
        const int s0 = jb_lo * 64;
        #pragma unroll
        for (int i = 0; i < 4; i++) {
            int idx = tid + i * 256;
            int r = idx >> 4, c4 = (idx & 15) * 4;
            cpasync16(kv_s0 + (uint32_t)(r * QSTR + c4) * 4,
                      Kg + (size_t)(s0 + r) * 64 + c4);
            cpasync16(kv_s0 + (uint32_t)(64 * QSTR + r * VSTR + c4) * 4,
                      Vg + (size_t)(s0 + r) * 64 + c4);
        }
        CP_COMMIT();
    }

    // stage Q (tf32 already)
    #pragma unroll
    for (int i = 0; i < 8; i++) {
        int idx = tid + i * 256;
        int r = idx >> 4, c4 = (idx & 15) * 4;
        *(uint4*)&Qs[r * QSTR + c4] = *(const uint4*)(Qg + (size_t)r * 64 + c4);
    }

    float o[8][4];
    #pragma unroll
    for (int nt = 0; nt < 8; nt++)
        #pragma unroll
        for (int l = 0; l < 4; l++) o[nt][l] = 0.f;
    float mi0 = -1e30f, mi1 = -1e30f, li0 = 0.f, li1 = 0.f;

    const int rg0 = t0 + r0 + g, rg1 = rg0 + 8;

    int buf = 0;
    for (int jb = jb_lo; jb <= jb_hi; jb++) {
        const int s0 = jb * 64;
        CP_WAIT0();
        __syncthreads();   // K/V(jb) visible; all warps done with other buffer

        if (jb + 1 <= jb_hi) {   // prefetch next block into other buffer
            const int sn = (jb + 1) * 64;
            const uint32_t kvb = kv_s0 + (uint32_t)((buf ^ 1) * KV_WORDS) * 4;
            #pragma unroll
            for (int i = 0; i < 4; i++) {
                int idx = tid + i * 256;
                int r = idx >> 4, c4 = (idx & 15) * 4;
                cpasync16(kvb + (uint32_t)(r * QSTR + c4) * 4,
                          Kg + (size_t)(sn + r) * 64 + c4);
                cpasync16(kvb + (uint32_t)(64 * QSTR + r * VSTR + c4) * 4,
                          Vg + (size_t)(sn + r) * 64 + c4);
            }
            CP_COMMIT();
        }

        const uint32_t* Ks = KV0 + buf * KV_WORDS;
        const uint32_t* Vs = Ks + 64 * QSTR;

        float s[8][4];
        #pragma unroll
        for (int nt = 0; nt < 8; nt++)
            #pragma unroll
            for (int l = 0; l < 4; l++) s[nt][l] = 0.f;
        #pragma unroll
        for (int ks = 0; ks < 8; ks++) {
            const int kb = ks * 8;
            uint32_t a[4];
            a[0] = Qs[(r0 + g    ) * QSTR + kb + t];
            a[1] = Qs[(r0 + g + 8) * QSTR + kb + t];
            a[2] = Qs[(r0 + g    ) * QSTR + kb + t + 4];
            a[3] = Qs[(r0 + g + 8) * QSTR + kb + t + 4];
            #pragma unroll
            for (int nt = 0; nt < 8; nt++) {
                uint32_t b[2];
                b[0] = Ks[(nt * 8 + g) * QSTR + kb + t];
                b[1] = Ks[(nt * 8 + g) * QSTR + kb + t + 4];
                mma_tf32_16n8k8(s[nt], a, b);
            }
        }

        float tm0 = -1e30f, tm1 = -1e30f;
        #pragma unroll
        for (int nt = 0; nt < 8; nt++) {
            int cg = s0 + nt * 8 + 2 * t;
            int d00 = rg0 - cg, d01 = d00 - 1;
            int d10 = rg1 - cg, d11 = d10 - 1;
            s[nt][0] = (d00 >= 0 && d00 < WIN) ? s[nt][0] * SCALE_F : -1e30f;
            s[nt][1] = (d01 >= 0 && d01 < WIN) ? s[nt][1] * SCALE_F : -1e30f;
            s[nt][2] = (d10 >= 0 && d10 < WIN) ? s[nt][2] * SCALE_F : -1e30f;
            s[nt][3] = (d11 >= 0 && d11 < WIN) ? s[nt][3] * SCALE_F : -1e30f;
            tm0 = fmaxf(tm0, fmaxf(s[nt][0], s[nt][1]));
            tm1 = fmaxf(tm1, fmaxf(s[nt][2], s[nt][3]));
        }
        tm0 = fmaxf(tm0, __shfl_xor_sync(0xffffffffu, tm0, 1));
        tm0 = fmaxf(tm0, __shfl_xor_sync(0xffffffffu, tm0, 2));
        tm1 = fmaxf(tm1, __shfl_xor_sync(0xffffffffu, tm1, 1));
        tm1 = fmaxf(tm1, __shfl_xor_sync(0xffffffffu, tm1, 2));

        float mn0 = fmaxf(mi0, tm0), mn1 = fmaxf(mi1, tm1);
        float al0 = __expf(mi0 - mn0), al1 = __expf(mi1 - mn1);
        mi0 = mn0; mi1 = mn1;
        float rs0 = 0.f, rs1 = 0.f;
        #pragma unroll
        for (int nt = 0; nt < 8; nt++) {
            float p00 = __expf(s[nt][0] - mn0);
            float p01 = __expf(s[nt][1] - mn0);
            float p10 = __expf(s[nt][2] - mn1);
            float p11 = __expf(s[nt][3] - mn1);
            rs0 += p00 + p01;
            rs1 += p10 + p11;
            int col = nt * 8 + 2 * t;
            *(uint2*)&Ps[(r0 + g    ) * QSTR + col] = make_uint2(f2tf(p00), f2tf(p01));
            *(uint2*)&Ps[(r0 + g + 8) * QSTR + col] = make_uint2(f2tf(p10), f2tf(p11));
            o[nt][0] *= al0; o[nt][1] *= al0;
            o[nt][2] *= al1; o[nt][3] *= al1;
        }
        rs0 += __shfl_xor_sync(0xffffffffu, rs0, 1);
        rs0 += __shfl_xor_sync(0xffffffffu, rs0, 2);
        rs1 += __shfl_xor_sync(0xffffffffu, rs1, 1);
        rs1 += __shfl_xor_sync(0xffffffffu, rs1, 2);
        li0 = li0 * al0 + rs0;
        li1 = li1 * al1 + rs1;
        __syncwarp();

        #pragma unroll
        for (int ks = 0; ks < 8; ks++) {
            const int kb = ks * 8;
            uint32_t a[4];
            a[0] = Ps[(r0 + g    ) * QSTR + kb + t];
            a[1] = Ps[(r0 + g + 8) * QSTR + kb + t];
            a[2] = Ps[(r0 + g    ) * QSTR + kb + t + 4];
            a[3] = Ps[(r0 + g + 8) * QSTR + kb + t + 4];
            #pragma unroll
            for (int nt = 0; nt < 8; nt++) {
                uint32_t b[2];
                b[0] = Vs[(kb + t    ) * VSTR + nt * 8 + g];
                b[1] = Vs[(kb + t + 4) * VSTR + nt * 8 + g];
                mma_tf32_16n8k8(o[nt], a, b);
            }
        }
        buf ^= 1;
    }

    float inv0 = 1.f / li0, inv1 = 1.f / li1;
    #pragma unroll
    for (int nt = 0; nt < 8; nt++) {
        int col = h * 64 + nt * 8 + 2 * t;
        *(uint2*)(g_att + (size_t)rg0 * CC + col) =
            make_uint2(f2tf(o[nt][0] * inv0), f2tf(o[nt][1] * inv0));
        *(uint2*)(g_att + (size_t)rg1 * CC + col) =
            make_uint2(f2tf(o[nt][2] * inv1), f2tf(o[nt][3] * inv1));
    }
}

// ---------------------------------------------------------------------------
extern "C" void kernel_launch(void* const* d_in, const int* in_sizes, int n_in,
                              void* d_out, int out_size)
{
    const float* x    = (const float*)d_in[0];
    const float* wqkv = (const float*)d_in[3];
    const float* wo   = (const float*)d_in[4];
    const float* qnw  = (const float*)d_in[5];
    const float* knw  = (const float*)d_in[6];
    const float* cosT = (const float*)d_in[7];
    const float* sinT = (const float*)d_in[8];
    float* out = (float*)d_out;

    float* p_qkv = nullptr;
    uint32_t *p_xt = nullptr, *p_wqkvt = nullptr, *p_wot = nullptr, *p_att = nullptr;
    cudaGetSymbolAddress((void**)&p_qkv, g_qkv);
    cudaGetSymbolAddress((void**)&p_xt, g_xt);
    cudaGetSymbolAddress((void**)&p_wqkvt, g_wqkvt);
    cudaGetSymbolAddress((void**)&p_wot, g_wot);
    cudaGetSymbolAddress((void**)&p_att, g_att);

    // 0) pre-convert fp32 -> tf32 (RN)
    cvt_tf32_k<<<(TT * CC / 4 + 255) / 256, 256>>>((const float4*)x, (uint4*)p_xt, TT * CC / 4);
    cvt_tf32_k<<<(3 * CC * CC / 4 + 255) / 256, 256>>>((const float4*)wqkv, (uint4*)p_wqkvt, 3 * CC * CC / 4);
    cvt_tf32_k<<<(CC * CC / 4 + 255) / 256, 256>>>((const float4*)wo, (uint4*)p_wot, CC * CC / 4);

    cudaFuncSetAttribute(gemm_mma, cudaFuncAttributeMaxDynamicSharedMemorySize, GSMEM_B);
    cudaFuncSetAttribute(attn_mma, cudaFuncAttributeMaxDynamicSharedMemorySize, ATT_SMEM);

    // 1) qkv = x @ w_qkv^T
    gemm_mma<<<dim3(3072 / 128, 4096 / 128), 256, GSMEM_B>>>(p_xt, p_wqkvt, p_qkv, TT, 3 * CC, CC);

    // 2) rmsnorm + rope + v*0.5 -> tf32 [H][T][64]
    qkv_post<<<TT, 512>>>(cosT, sinT, qnw, knw);

    // 3) sliding-window attention -> tf32 att
    attn_mma<<<dim3(TT / 128, HH), 256, ATT_SMEM>>>();

    // 4) out = att @ w_o^T
    gemm_mma<<<dim3(1024 / 128, 4096 / 128), 256, GSMEM_B>>>(p_att, p_wot, out, TT, CC, CC);
}

// round 12
// speedup vs baseline: 1.0986x; 1.0986x over previous
#include <cuda_runtime.h>
#include <cuda_bf16.h>
#include <cstdint>
#include <math.h>

#define TT   4096
#define CC   1024
#define HH   16
#define DD   64
#define WIN  1024
#define SCALE_F 0.12f

// scratch (allocation-free contract: __device__ globals)
__device__ float    g_qkv[TT * 3 * CC];     // fp32 qkv projection output (logical)
__device__ uint32_t g_q[HH * TT * DD];      // tf32, logical layout
__device__ uint32_t g_k[HH * TT * DD];
__device__ uint32_t g_v[HH * TT * DD];
__device__ uint32_t g_att[TT * CC];         // tf32, PAIR-PERMUTED k-blocks
__device__ uint32_t g_xt[TT * CC];          // tf32, pair-permuted
__device__ uint32_t g_wqkvt[3 * CC * CC];   // tf32, pair-permuted
__device__ uint32_t g_wot[CC * CC];         // tf32, pair-permuted

__device__ __forceinline__ uint32_t f2tf(float f) {
    uint32_t u;
    asm("cvt.rn.tf32.f32 %0, %1;" : "=r"(u) : "f"(f));
    return u;
}

__device__ __forceinline__ void mma_tf32_16n8k8(float* c, const uint32_t* a,
                                                const uint32_t* b) {
    asm volatile(
        "mma.sync.aligned.m16n8k8.row.col.f32.tf32.tf32.f32 "
        "{%0,%1,%2,%3}, {%4,%5,%6,%7}, {%8,%9}, {%0,%1,%2,%3};"
        : "+f"(c[0]), "+f"(c[1]), "+f"(c[2]), "+f"(c[3])
        : "r"(a[0]), "r"(a[1]), "r"(a[2]), "r"(a[3]), "r"(b[0]), "r"(b[1]));
}

__device__ __forceinline__ void cpasync16(uint32_t saddr, const void* g) {
    asm volatile("cp.async.cg.shared.global [%0], [%1], 16;"
                 :: "r"(saddr), "l"(g) : "memory");
}
#define CP_COMMIT() asm volatile("cp.async.commit_group;" ::: "memory")
#define CP_WAIT0()  asm volatile("cp.async.wait_group 0;" ::: "memory")

// ---------------------------------------------------------------------------
// fp32 -> tf32 bulk convert with pair-permuted k-blocks:
// within each 8-col block, logical col l stored at (l<4 ? 2l : 2(l-4)+1).
// ---------------------------------------------------------------------------
__global__ void cvt_tf32_perm(const float4* __restrict__ in,
                              uint32_t* __restrict__ out, int n4)
{
    int i = blockIdx.x * 256 + threadIdx.x;
    if (i >= n4) return;
    float4 v = in[i];
    int e0  = i * 4;               // logical element index (4-aligned)
    int blk = e0 & ~7;             // 8-block base
    int off = (e0 & 4) ? 1 : 0;    // low half -> even slots, high half -> odd
    out[blk + off + 0] = f2tf(v.x);
    out[blk + off + 2] = f2tf(v.y);
    out[blk + off + 4] = f2tf(v.z);
    out[blk + off + 6] = f2tf(v.w);
}

// ===========================================================================
// C[M,N] = A[M,K] * B[N,K]^T; A/B tf32 pair-permuted in global.
// 128x128 CTA tile, 128 threads = 4 warps (2x2), warp tile 64x64.
// 2-stage cp.async, K-chunk 32. Fragment loads are conflict-free LDS.64.
// ===========================================================================
#define SSTR  40                      // words per smem row (== 8 mod 32)
#define CHUNK (128 * SSTR)            // words per operand per stage
#define GSTAGE (2 * CHUNK)
#define GSMEM_B (2 * GSTAGE * 4)      // 81920 bytes

__global__ __launch_bounds__(128, 2)
void gemm_mma(const uint32_t* __restrict__ A, const uint32_t* __restrict__ B,
              float* __restrict__ C, int M, int N, int K)
{
    extern __shared__ uint32_t smg[];   // [2 stages][A CHUNK | B CHUNK]

    const int tid = threadIdx.x;
    const int wid = tid >> 5, lid = tid & 31;
    const int g = lid >> 2, t = lid & 3;
    const int wm = wid >> 1, wn = wid & 1;   // 2x2 warps, warp tile 64x64
    const int bm = blockIdx.y * 128, bn = blockIdx.x * 128;

    const int srow = tid >> 3, sc4 = (tid & 7) * 4;   // staging: 16 rows/pass

    float acc[4][8][4];
    #pragma unroll
    for (int i = 0; i < 4; i++)
        #pragma unroll
        for (int j = 0; j < 8; j++)
            #pragma unroll
            for (int l = 0; l < 4; l++) acc[i][j][l] = 0.f;

    const uint32_t* Agb = A + (size_t)bm * K;
    const uint32_t* Bgb = B + (size_t)bn * K;
    const uint32_t smem0 = (uint32_t)__cvta_generic_to_shared(smg);

    // prologue: chunk 0 -> stage 0
    {
        uint32_t sA = smem0, sB = smem0 + CHUNK * 4;
        #pragma unroll
        for (int i = 0; i < 8; i++) {
            int row = srow + i * 16;
            uint32_t so = (uint32_t)(row * SSTR + sc4) * 4;
            cpasync16(sA + so, Agb + (size_t)row * K + sc4);
            cpasync16(sB + so, Bgb + (size_t)row * K + sc4);
        }
        CP_COMMIT();
    }

    const int nc = K / 32;
    for (int c = 0; c < nc; c++) {
        CP_WAIT0();
        __syncthreads();   // chunk c visible; prev compute on other stage done

        if (c + 1 < nc) {
            uint32_t sA = smem0 + ((c + 1) & 1) * GSTAGE * 4;
            uint32_t sB = sA + CHUNK * 4;
            const uint32_t* Ag = Agb + (c + 1) * 32;
            const uint32_t* Bg = Bgb + (c + 1) * 32;
            #pragma unroll
            for (int i = 0; i < 8; i++) {
                int row = srow + i * 16;
                uint32_t so = (uint32_t)(row * SSTR + sc4) * 4;
                cpasync16(sA + so, Ag + (size_t)row * K + sc4);
                cpasync16(sB + so, Bg + (size_t)row * K + sc4);
            }
            CP_COMMIT();
        }

        const uint32_t* As = smg + (c & 1) * GSTAGE;
        const uint32_t* Bs = As + CHUNK;

        #pragma unroll
        for (int ks = 0; ks < 4; ks++) {
            const int kb = ks * 8;
            // A fragments: LDS.64 per row gives (k=t, k=t+4)
            uint32_t af[4][4];
            #pragma unroll
            for (int mt = 0; mt < 4; mt++) {
                int r = wm * 64 + mt * 16 + g;
                uint2 lo = *(const uint2*)&As[(r    ) * SSTR + kb + 2 * t];
                uint2 hi = *(const uint2*)&As[(r + 8) * SSTR + kb + 2 * t];
                af[mt][0] = lo.x; af[mt][1] = hi.x;
                af[mt][2] = lo.y; af[mt][3] = hi.y;
            }
            // B fragments: LDS.64 gives (b0, b1)
            uint32_t bf[8][2];
            #pragma unroll
            for (int nt = 0; nt < 8; nt++) {
                int n0 = wn * 64 + nt * 8 + g;
                uint2 bb = *(const uint2*)&Bs[n0 * SSTR + kb + 2 * t];
                bf[nt][0] = bb.x; bf[nt][1] = bb.y;
            }
            #pragma unroll
            for (int mt = 0; mt < 4; mt++)
                #pragma unroll
                for (int nt = 0; nt < 8; nt++)
                    mma_tf32_16n8k8(acc[mt][nt], af[mt], bf[nt]);
        }
    }

    #pragma unroll
    for (int mt = 0; mt < 4; mt++) {
        int row0 = bm + wm * 64 + mt * 16 + g;
        #pragma unroll
        for (int nt = 0; nt < 8; nt++) {
            int col = bn + wn * 64 + nt * 8 + 2 * t;
            *(float2*)(C + (size_t)row0 * N + col) =
                make_float2(acc[mt][nt][0], acc[mt][nt][1]);
            *(float2*)(C + (size_t)(row0 + 8) * N + col) =
                make_float2(acc[mt][nt][2], acc[mt][nt][3]);
        }
    }
}

// ---------------------------------------------------------------------------
// Split qkv row into per-head Q/K/V with RMSNorm + RoPE (Q,K) and 0.5*V.
// Outputs tf32, logical layout (consumed by attention).
// ---------------------------------------------------------------------------
__global__ void qkv_post(const float* __restrict__ cosT, const float* __restrict__ sinT,
                         const float* __restrict__ qw, const float* __restrict__ kw)
{
    const int t    = blockIdx.x;
    const int h    = threadIdx.x >> 5;
    const int lane = threadIdx.x & 31;
    const int d0   = lane * 2;
    const float* row = g_qkv + (size_t)t * (3 * CC);

    float cv = 0.f, sv = 0.f;
    if (lane < 16) { cv = cosT[t * 16 + lane]; sv = sinT[t * 16 + lane]; }

    float2 q2 = *(const float2*)(row + h * 64 + d0);
    float ss = q2.x * q2.x + q2.y * q2.y;
    #pragma unroll
    for (int off = 16; off; off >>= 1) ss += __shfl_xor_sync(0xffffffffu, ss, off);
    float rn = rsqrtf(ss * (1.f / 64.f) + 1e-6f);
    float qa = q2.x * rn * qw[d0];
    float qb = q2.y * rn * qw[d0 + 1];
    if (lane < 16) {
        float e = qa, od = qb;
        qa = e * cv - od * sv;
        qb = e * sv + od * cv;
    }
    *(uint2*)(g_q + ((size_t)h * TT + t) * 64 + d0) = make_uint2(f2tf(qa), f2tf(qb));

    float2 k2 = *(const float2*)(row + CC + h * 64 + d0);
    float ssk = k2.x * k2.x + k2.y * k2.y;
    #pragma unroll
    for (int off = 16; off; off >>= 1) ssk += __shfl_xor_sync(0xffffffffu, ssk, off);
    float rk = rsqrtf(ssk * (1.f / 64.f) + 1e-6f);
    float ka = k2.x * rk * kw[d0];
    float kb = k2.y * rk * kw[d0 + 1];
    if (lane < 16) {
        float e = ka, od = kb;
        ka = e * cv - od * sv;
        kb = e * sv + od * cv;
    }
    *(uint2*)(g_k + ((size_t)h * TT + t) * 64 + d0) = make_uint2(f2tf(ka), f2tf(kb));

    float2 v2 = *(const float2*)(row + 2 * CC + h * 64 + d0);
    *(uint2*)(g_v + ((size_t)h * TT + t) * 64 + d0) =
        make_uint2(f2tf(v2.x * 0.5f), f2tf(v2.y * 0.5f));
}

// ===========================================================================
// Sliding-window flash attention on tensor pipe (mma.sync tf32).
// cp.async double-buffered K/V. 128 queries x 1 head per CTA, 8 warps.
// Epilogue writes g_att PAIR-PERMUTED for the O-projection GEMM.
// ===========================================================================
#define QSTR 68
#define VSTR 72
#define KV_WORDS (64 * QSTR + 64 * VSTR)
#define ATT_SMEM ((128 * QSTR + 128 * QSTR + 2 * KV_WORDS) * 4)

__global__ __launch_bounds__(256, 1)
void attn_mma()
{
    extern __shared__ uint32_t sm4[];
    uint32_t* Qs  = sm4;                    // [128][68]
    uint32_t* Ps  = Qs + 128 * QSTR;        // [128][68]
    uint32_t* KV0 = Ps + 128 * QSTR;        // [2][ Ks 64x68 | Vs 64x72 ]

    const int h  = blockIdx.y;
    const int qb = blockIdx.x;
    const int t0 = qb * 128;
    const int tid = threadIdx.x;
    const int wid = tid >> 5, lid = tid & 31;
    const int g = lid >> 2, t = lid & 3;
    const int r0 = wid * 16;

    const uint32_t* Qg = g_q + ((size_t)h * TT + t0) * 64;
    const uint32_t* Kg = g_k + (size_t)h * TT * 64;
    const uint32_t* Vg = g_v + (size_t)h * TT * 64;
    const uint32_t kv_s0 = (uint32_t)__cvta_generic_to_shared(KV0);

    int jb_lo = 2 * qb - 16; if (jb_lo < 0) jb_lo = 0;
    const int jb_hi = 2 * qb + 1;

    {
        const int s0 = jb_lo * 64;
        #pragma unroll
        for (int i = 0; i < 4; i++) {
            int idx = tid + i * 256;
            int r = idx >> 4, c4 = (idx & 15) * 4;
            cpasync16(kv_s0 + (uint32_t)(r * QSTR + c4) * 4,
                      Kg + (size_t)(s0 + r) * 64 + c4);
            cpasync16(kv_s0 + (uint32_t)(64 * QSTR + r * VSTR + c4) * 4,
                      Vg + (size_t)(s0 + r) * 64 + c4);
        }
        CP_COMMIT();
    }

    #pragma unroll
    for (int i = 0; i < 8; i++) {
        int idx = tid + i * 256;
        int r = idx >> 4, c4 = (idx & 15) * 4;
        *(uint4*)&Qs[r * QSTR + c4] = *(const uint4*)(Qg + (size_t)r * 64 + c4);
    }

    float o[8][4];
    #pragma unroll
    for (int nt = 0; nt < 8; nt++)
        #pragma unroll
        for (int l = 0; l < 4; l++) o[nt][l] = 0.f;
    float mi0 = -1e30f, mi1 = -1e30f, li0 = 0.f, li1 = 0.f;

    const int rg0 = t0 + r0 + g, rg1 = rg0 + 8;

    int buf = 0;
    for (int jb = jb_lo; jb <= jb_hi; jb++) {
        const int s0 = jb * 64;
        CP_WAIT0();
        __syncthreads();

        if (jb + 1 <= jb_hi) {
            const int sn = (jb + 1) * 64;
            const uint32_t kvb = kv_s0 + (uint32_t)((buf ^ 1) * KV_WORDS) * 4;
            #pragma unroll
            for (int i = 0; i < 4; i++) {
                int idx = tid + i * 256;
                int r = idx >> 4, c4 = (idx & 15) * 4;
                cpasync16(kvb + (uint32_t)(r * QSTR + c4) * 4,
                          Kg + (size_t)(sn + r) * 64 + c4);
                cpasync16(kvb + (uint32_t)(64 * QSTR + r * VSTR + c4) * 4,
                          Vg + (size_t)(sn + r) * 64 + c4);
            }
            CP_COMMIT();
        }

        const uint32_t* Ks = KV0 + buf * KV_WORDS;
        const uint32_t* Vs = Ks + 64 * QSTR;

        float s[8][4];
        #pragma unroll
        for (int nt = 0; nt < 8; nt++)
            #pragma unroll
            for (int l = 0; l < 4; l++) s[nt][l] = 0.f;
        #pragma unroll
        for (int ks = 0; ks < 8; ks++) {
            const int kb = ks * 8;
            uint32_t a[4];
            a[0] = Qs[(r0 + g    ) * QSTR + kb + t];
            a[1] = Qs[(r0 + g + 8) * QSTR + kb + t];
            a[2] = Qs[(r0 + g    ) * QSTR + kb + t + 4];
            a[3] = Qs[(r0 + g + 8) * QSTR + kb + t + 4];
            #pragma unroll
            for (int nt = 0; nt < 8; nt++) {
                uint32_t b[2];
                b[0] = Ks[(nt * 8 + g) * QSTR + kb + t];
                b[1] = Ks[(nt * 8 + g) * QSTR + kb + t + 4];
                mma_tf32_16n8k8(s[nt], a, b);
            }
        }

        float tm0 = -1e30f, tm1 = -1e30f;
        #pragma unroll
        for (int nt = 0; nt < 8; nt++) {
            int cg = s0 + nt * 8 + 2 * t;
            int d00 = rg0 - cg, d01 = d00 - 1;
            int d10 = rg1 - cg, d11 = d10 - 1;
            s[nt][0] = (d00 >= 0 && d00 < WIN) ? s[nt][0] * SCALE_F : -1e30f;
            s[nt][1] = (d01 >= 0 && d01 < WIN) ? s[nt][1] * SCALE_F : -1e30f;
            s[nt][2] = (d10 >= 0 && d10 < WIN) ? s[nt][2] * SCALE_F : -1e30f;
            s[nt][3] = (d11 >= 0 && d11 < WIN) ? s[nt][3] * SCALE_F : -1e30f;
            tm0 = fmaxf(tm0, fmaxf(s[nt][0], s[nt][1]));
            tm1 = fmaxf(tm1, fmaxf(s[nt][2], s[nt][3]));
        }
        tm0 = fmaxf(tm0, __shfl_xor_sync(0xffffffffu, tm0, 1));
        tm0 = fmaxf(tm0, __shfl_xor_sync(0xffffffffu, tm0, 2));
        tm1 = fmaxf(tm1, __shfl_xor_sync(0xffffffffu, tm1, 1));
        tm1 = fmaxf(tm1, __shfl_xor_sync(0xffffffffu, tm1, 2));

        float mn0 = fmaxf(mi0, tm0), mn1 = fmaxf(mi1, tm1);
        float al0 = __expf(mi0 - mn0), al1 = __expf(mi1 - mn1);
        mi0 = mn0; mi1 = mn1;
        float rs0 = 0.f, rs1 = 0.f;
        #pragma unroll
        for (int nt = 0; nt < 8; nt++) {
            float p00 = __expf(s[nt][0] - mn0);
            float p01 = __expf(s[nt][1] - mn0);
            float p10 = __expf(s[nt][2] - mn1);
            float p11 = __expf(s[nt][3] - mn1);
            rs0 += p00 + p01;
            rs1 += p10 + p11;
            int col = nt * 8 + 2 * t;
            *(uint2*)&Ps[(r0 + g    ) * QSTR + col] = make_uint2(f2tf(p00), f2tf(p01));
            *(uint2*)&Ps[(r0 + g + 8) * QSTR + col] = make_uint2(f2tf(p10), f2tf(p11));
            o[nt][0] *= al0; o[nt][1] *= al0;
            o[nt][2] *= al1; o[nt][3] *= al1;
        }
        rs0 += __shfl_xor_sync(0xffffffffu, rs0, 1);
        rs0 += __shfl_xor_sync(0xffffffffu, rs0, 2);
        rs1 += __shfl_xor_sync(0xffffffffu, rs1, 1);
        rs1 += __shfl_xor_sync(0xffffffffu, rs1, 2);
        li0 = li0 * al0 + rs0;
        li1 = li1 * al1 + rs1;
        __syncwarp();

        #pragma unroll
        for (int ks = 0; ks < 8; ks++) {
            const int kb = ks * 8;
            uint32_t a[4];
            a[0] = Ps[(r0 + g    ) * QSTR + kb + t];
            a[1] = Ps[(r0 + g + 8) * QSTR + kb + t];
            a[2] = Ps[(r0 + g    ) * QSTR + kb + t + 4];
            a[3] = Ps[(r0 + g + 8) * QSTR + kb + t + 4];
            #pragma unroll
            for (int nt = 0; nt < 8; nt++) {
                uint32_t b[2];
                b[0] = Vs[(kb + t    ) * VSTR + nt * 8 + g];
                b[1] = Vs[(kb + t + 4) * VSTR + nt * 8 + g];
                mma_tf32_16n8k8(o[nt], a, b);
            }
        }
        buf ^= 1;
    }

    // epilogue: normalize; store PAIR-PERMUTED tf32 for the O-proj GEMM.
    // logical pair (2t, 2t+1) within the 8-block -> storage (base, base+2).
    float inv0 = 1.f / li0, inv1 = 1.f / li1;
    const int sb_off = (t < 2) ? 4 * t : 4 * t - 7;
    #pragma unroll
    for (int nt = 0; nt < 8; nt++) {
        int sb = h * 64 + nt * 8 + sb_off;
        g_att[(size_t)rg0 * CC + sb]     = f2tf(o[nt][0] * inv0);
        g_att[(size_t)rg0 * CC + sb + 2] = f2tf(o[nt][1] * inv0);
        g_att[(size_t)rg1 * CC + sb]     = f2tf(o[nt][2] * inv1);
        g_att[(size_t)rg1 * CC + sb + 2] = f2tf(o[nt][3] * inv1);
    }
}

// ---------------------------------------------------------------------------
extern "C" void kernel_launch(void* const* d_in, const int* in_sizes, int n_in,
                              void* d_out, int out_size)
{
    const float* x    = (const float*)d_in[0];
    const float* wqkv = (const float*)d_in[3];
    const float* wo   = (const float*)d_in[4];
    const float* qnw  = (const float*)d_in[5];
    const float* knw  = (const float*)d_in[6];
    const float* cosT = (const float*)d_in[7];
    const float* sinT = (const float*)d_in[8];
    float* out = (float*)d_out;

    float* p_qkv = nullptr;
    uint32_t *p_xt = nullptr, *p_wqkvt = nullptr, *p_wot = nullptr, *p_att = nullptr;
    cudaGetSymbolAddress((void**)&p_qkv, g_qkv);
    cudaGetSymbolAddress((void**)&p_xt, g_xt);
    cudaGetSymbolAddress((void**)&p_wqkvt, g_wqkvt);
    cudaGetSymbolAddress((void**)&p_wot, g_wot);
    cudaGetSymbolAddress((void**)&p_att, g_att);

    // 0) pre-convert fp32 -> tf32 (RN), pair-permuted k-blocks
    cvt_tf32_perm<<<(TT * CC / 4 + 255) / 256, 256>>>((const float4*)x, p_xt, TT * CC / 4);
    cvt_tf32_perm<<<(3 * CC * CC / 4 + 255) / 256, 256>>>((const float4*)wqkv, p_wqkvt, 3 * CC * CC / 4);
    cvt_tf32_perm<<<(CC * CC / 4 + 255) / 256, 256>>>((const float4*)wo, p_wot, CC * CC / 4);

    cudaFuncSetAttribute(gemm_mma, cudaFuncAttributeMaxDynamicSharedMemorySize, GSMEM_B);
    cudaFuncSetAttribute(attn_mma, cudaFuncAttributeMaxDynamicSharedMemorySize, ATT_SMEM);

    // 1) qkv = x @ w_qkv^T
    gemm_mma<<<dim3(3072 / 128, 4096 / 128), 128, GSMEM_B>>>(p_xt, p_wqkvt, p_qkv, TT, 3 * CC, CC);

    // 2) rmsnorm + rope + v*0.5 -> tf32 [H][T][64]
    qkv_post<<<TT, 512>>>(cosT, sinT, qnw, knw);

    // 3) sliding-window attention -> tf32 att (pair-permuted)
    attn_mma<<<dim3(TT / 128, HH), 256, ATT_SMEM>>>();

    // 4) out = att @ w_o^T
    gemm_mma<<<dim3(1024 / 128, 4096 / 128), 128, GSMEM_B>>>(p_att, p_wot, out, TT, CC, CC);
}

// round 15
// speedup vs baseline: 1.1163x; 1.0161x over previous
#include <cuda_runtime.h>
#include <cuda_bf16.h>
#include <cstdint>
#include <math.h>

#define TT   4096
#define CC   1024
#define HH   16
#define DD   64
#define WIN  1024
#define SCALE_F 0.12f
#define LOG2E 1.4426950408889634f

// scratch (allocation-free contract: __device__ globals)
__device__ float    g_qkv[TT * 3 * CC];     // fp32 qkv projection output (logical)
__device__ uint32_t g_q[HH * TT * DD];      // tf32, pair-permuted d, pre-scaled
__device__ uint32_t g_k[HH * TT * DD];      // tf32, pair-permuted d
__device__ uint32_t g_v[HH * TT * DD];      // tf32, logical
__device__ uint32_t g_att[TT * CC];         // tf32, pair-permuted k-blocks
__device__ uint32_t g_xt[TT * CC];          // tf32, pair-permuted
__device__ uint32_t g_wqkvt[3 * CC * CC];   // tf32, pair-permuted
__device__ uint32_t g_wot[CC * CC];         // tf32, pair-permuted

__device__ __forceinline__ uint32_t f2tf(float f) {
    uint32_t u;
    asm("cvt.rn.tf32.f32 %0, %1;" : "=r"(u) : "f"(f));
    return u;
}

__device__ __forceinline__ void mma_tf32_16n8k8(float* c, const uint32_t* a,
                                                const uint32_t* b) {
    asm volatile(
        "mma.sync.aligned.m16n8k8.row.col.f32.tf32.tf32.f32 "
        "{%0,%1,%2,%3}, {%4,%5,%6,%7}, {%8,%9}, {%0,%1,%2,%3};"
        : "+f"(c[0]), "+f"(c[1]), "+f"(c[2]), "+f"(c[3])
        : "r"(a[0]), "r"(a[1]), "r"(a[2]), "r"(a[3]), "r"(b[0]), "r"(b[1]));
}

__device__ __forceinline__ void cpasync16(uint32_t saddr, const void* g) {
    asm volatile("cp.async.cg.shared.global [%0], [%1], 16;"
                 :: "r"(saddr), "l"(g) : "memory");
}
#define CP_COMMIT() asm volatile("cp.async.commit_group;" ::: "memory")
#define CP_WAIT0()  asm volatile("cp.async.wait_group 0;" ::: "memory")

// ---------------------------------------------------------------------------
// fp32 -> tf32 bulk convert with pair-permuted 8-blocks:
// logical col l -> storage (l%8<4 ? 2(l%8) : 2(l%8-4)+1) within the block.
// ---------------------------------------------------------------------------
__global__ void cvt_tf32_perm(const float4* __restrict__ in,
                              uint32_t* __restrict__ out, int n4)
{
    int i = blockIdx.x * 256 + threadIdx.x;
    if (i >= n4) return;
    float4 v = in[i];
    int e0  = i * 4;
    int blk = e0 & ~7;
    int off = (e0 & 4) ? 1 : 0;
    out[blk + off + 0] = f2tf(v.x);
    out[blk + off + 2] = f2tf(v.y);
    out[blk + off + 4] = f2tf(v.z);
    out[blk + off + 6] = f2tf(v.w);
}

// ===========================================================================
// C[M,N] = A[M,K] * B[N,K]^T; A/B tf32 pair-permuted in global.
// 128x128 CTA tile, 256 threads = 8 warps (2 m x 4 n), warp tile 64x32.
// 2-stage cp.async, K-chunk 32, conflict-free LDS.64 fragments.
// ===========================================================================
#define SSTR  40
#define CHUNK (128 * SSTR)
#define GSTAGE (2 * CHUNK)
#define GSMEM_B (2 * GSTAGE * 4)      // 81920 bytes

__global__ __launch_bounds__(256, 2)
void gemm_mma(const uint32_t* __restrict__ A, const uint32_t* __restrict__ B,
              float* __restrict__ C, int M, int N, int K)
{
    extern __shared__ uint32_t smg[];

    const int tid = threadIdx.x;
    const int wid = tid >> 5, lid = tid & 31;
    const int g = lid >> 2, t = lid & 3;
    const int wm = wid & 1, wn = wid >> 1;   // 2x4 warps, warp tile 64x32
    const int bm = blockIdx.y * 128, bn = blockIdx.x * 128;

    const int srow = tid >> 3, sc4 = (tid & 7) * 4;   // staging: 32 rows/pass

    float acc[4][4][4];
    #pragma unroll
    for (int i = 0; i < 4; i++)
        #pragma unroll
        for (int j = 0; j < 4; j++)
            #pragma unroll
            for (int l = 0; l < 4; l++) acc[i][j][l] = 0.f;

    const uint32_t* Agb = A + (size_t)bm * K;
    const uint32_t* Bgb = B + (size_t)bn * K;
    const uint32_t smem0 = (uint32_t)__cvta_generic_to_shared(smg);

    // prologue: chunk 0 -> stage 0
    {
        uint32_t sA = smem0, sB = smem0 + CHUNK * 4;
        #pragma unroll
        for (int i = 0; i < 4; i++) {
            int row = srow + i * 32;
            uint32_t so = (uint32_t)(row * SSTR + sc4) * 4;
            cpasync16(sA + so, Agb + (size_t)row * K + sc4);
            cpasync16(sB + so, Bgb + (size_t)row * K + sc4);
        }
        CP_COMMIT();
    }

    const int nc = K / 32;
    for (int c = 0; c < nc; c++) {
        CP_WAIT0();
        __syncthreads();

        if (c + 1 < nc) {
            uint32_t sA = smem0 + ((c + 1) & 1) * GSTAGE * 4;
            uint32_t sB = sA + CHUNK * 4;
            const uint32_t* Ag = Agb + (c + 1) * 32;
            const uint32_t* Bg = Bgb + (c + 1) * 32;
            #pragma unroll
            for (int i = 0; i < 4; i++) {
                int row = srow + i * 32;
                uint32_t so = (uint32_t)(row * SSTR + sc4) * 4;
                cpasync16(sA + so, Ag + (size_t)row * K + sc4);
                cpasync16(sB + so, Bg + (size_t)row * K + sc4);
            }
            CP_COMMIT();
        }

        const uint32_t* As = smg + (c & 1) * GSTAGE;
        const uint32_t* Bs = As + CHUNK;

        #pragma unroll
        for (int ks = 0; ks < 4; ks++) {
            const int kb = ks * 8;
            uint32_t af[4][4];
            #pragma unroll
            for (int mt = 0; mt < 4; mt++) {
                int r = wm * 64 + mt * 16 + g;
                uint2 lo = *(const uint2*)&As[(r    ) * SSTR + kb + 2 * t];
                uint2 hi = *(const uint2*)&As[(r + 8) * SSTR + kb + 2 * t];
                af[mt][0] = lo.x; af[mt][1] = hi.x;
                af[mt][2] = lo.y; af[mt][3] = hi.y;
            }
            uint32_t bf[4][2];
            #pragma unroll
            for (int nt = 0; nt < 4; nt++) {
                int n0 = wn * 32 + nt * 8 + g;
                uint2 bb = *(const uint2*)&Bs[n0 * SSTR + kb + 2 * t];
                bf[nt][0] = bb.x; bf[nt][1] = bb.y;
            }
            #pragma unroll
            for (int mt = 0; mt < 4; mt++)
                #pragma unroll
                for (int nt = 0; nt < 4; nt++)
                    mma_tf32_16n8k8(acc[mt][nt], af[mt], bf[nt]);
        }
    }

    #pragma unroll
    for (int mt = 0; mt < 4; mt++) {
        int row0 = bm + wm * 64 + mt * 16 + g;
        #pragma unroll
        for (int nt = 0; nt < 4; nt++) {
            int col = bn + wn * 32 + nt * 8 + 2 * t;
            *(float2*)(C + (size_t)row0 * N + col) =
                make_float2(acc[mt][nt][0], acc[mt][nt][1]);
            *(float2*)(C + (size_t)(row0 + 8) * N + col) =
                make_float2(acc[mt][nt][2], acc[mt][nt][3]);
        }
    }
}

// ---------------------------------------------------------------------------
// RMSNorm + RoPE (Q,K) + 0.5*V. Q/K written PAIR-PERMUTED along d;
// Q pre-scaled by SCALE*log2(e) for the exp2 softmax. V logical.
// ---------------------------------------------------------------------------
__global__ void qkv_post(const float* __restrict__ cosT, const float* __restrict__ sinT,
                         const float* __restrict__ qw, const float* __restrict__ kw)
{
    const int t    = blockIdx.x;
    const int h    = threadIdx.x >> 5;
    const int lane = threadIdx.x & 31;
    const int d0   = lane * 2;
    const float* row = g_qkv + (size_t)t * (3 * CC);

    // permuted slot for logical pair (d0, d0+1): base+s0, base+s0+2
    const int l = d0 & 7;
    const int s0 = (l < 4) ? (2 * l) : (2 * l - 7);
    const int pb = (d0 & ~7) + s0;

    float cv = 0.f, sv = 0.f;
    if (lane < 16) { cv = cosT[t * 16 + lane]; sv = sinT[t * 16 + lane]; }

    float2 q2 = *(const float2*)(row + h * 64 + d0);
    float ss = q2.x * q2.x + q2.y * q2.y;
    #pragma unroll
    for (int off = 16; off; off >>= 1) ss += __shfl_xor_sync(0xffffffffu, ss, off);
    float rn = rsqrtf(ss * (1.f / 64.f) + 1e-6f);
    float qa = q2.x * rn * qw[d0];
    float qb = q2.y * rn * qw[d0 + 1];
    if (lane < 16) {
        float e = qa, od = qb;
        qa = e * cv - od * sv;
        qb = e * sv + od * cv;
    }
    qa *= SCALE_F * LOG2E;
    qb *= SCALE_F * LOG2E;
    uint32_t* qo = g_q + ((size_t)h * TT + t) * 64 + pb;
    qo[0] = f2tf(qa); qo[2] = f2tf(qb);

    float2 k2 = *(const float2*)(row + CC + h * 64 + d0);
    float ssk = k2.x * k2.x + k2.y * k2.y;
    #pragma unroll
    for (int off = 16; off; off >>= 1) ssk += __shfl_xor_sync(0xffffffffu, ssk, off);
    float rk = rsqrtf(ssk * (1.f / 64.f) + 1e-6f);
    float ka = k2.x * rk * kw[d0];
    float kb = k2.y * rk * kw[d0 + 1];
    if (lane < 16) {
        float e = ka, od = kb;
        ka = e * cv - od * sv;
        kb = e * sv + od * cv;
    }
    uint32_t* ko = g_k + ((size_t)h * TT + t) * 64 + pb;
    ko[0] = f2tf(ka); ko[2] = f2tf(kb);

    float2 v2 = *(const float2*)(row + 2 * CC + h * 64 + d0);
    *(uint2*)(g_v + ((size_t)h * TT + t) * 64 + d0) =
        make_uint2(f2tf(v2.x * 0.5f), f2tf(v2.y * 0.5f));
}

// ===========================================================================
// Sliding-window flash attention (mma.sync tf32), exp2 softmax.
// Q/K pair-permuted -> LDS.64 S-phase fragments. cp.async dbl-buffered K/V.
// ===========================================================================
#define QSTR 72
#define VSTR 72
#define KV_WORDS (64 * QSTR + 64 * VSTR)
#define ATT_SMEM ((128 * QSTR + 128 * QSTR + 2 * KV_WORDS) * 4)   // 147456

__global__ __launch_bounds__(256, 1)
void attn_mma()
{
    extern __shared__ uint32_t sm4[];
    uint32_t* Qs  = sm4;                    // [128][72] permuted d
    uint32_t* Ps  = Qs + 128 * QSTR;        // [128][72] logical
    uint32_t* KV0 = Ps + 128 * QSTR;        // [2][ K 64x72 perm | V 64x72 logical ]

    const int h  = blockIdx.y;
    const int qb = blockIdx.x;
    const int t0 = qb * 128;
    const int tid = threadIdx.x;
    const int wid = tid >> 5, lid = tid & 31;
    const int g = lid >> 2, t = lid & 3;
    const int r0 = wid * 16;

    const uint32_t* Qg = g_q + ((size_t)h * TT + t0) * 64;
    const uint32_t* Kg = g_k + (size_t)h * TT * 64;
    const uint32_t* Vg = g_v + (size_t)h * TT * 64;
    const uint32_t kv_s0 = (uint32_t)__cvta_generic_to_shared(KV0);

    int jb_lo = 2 * qb - 16; if (jb_lo < 0) jb_lo = 0;
    const int jb_hi = 2 * qb + 1;

    {
        const int s0 = jb_lo * 64;
        #pragma unroll
        for (int i = 0; i < 4; i++) {
            int idx = tid + i * 256;
            int r = idx >> 4, c4 = (idx & 15) * 4;
            cpasync16(kv_s0 + (uint32_t)(r * QSTR + c4) * 4,
                      Kg + (size_t)(s0 + r) * 64 + c4);
            cpasync16(kv_s0 + (uint32_t)(64 * QSTR + r * VSTR + c4) * 4,
                      Vg + (size_t)(s0 + r) * 64 + c4);
        }
        CP_COMMIT();
    }

    #pragma unroll
    for (int i = 0; i < 8; i++) {
        int idx = tid + i * 256;
        int r = idx >> 4, c4 = (idx & 15) * 4;
        *(uint4*)&Qs[r * QSTR + c4] = *(const uint4*)(Qg + (size_t)r * 64 + c4);
    }

    float o[8][4];
    #pragma unroll
    for (int nt = 0; nt < 8; nt++)
        #pragma unroll
        for (int l = 0; l < 4; l++) o[nt][l] = 0.f;
    float mi0 = -1e30f, mi1 = -1e30f, li0 = 0.f, li1 = 0.f;

    const int rg0 = t0 + r0 + g, rg1 = rg0 + 8;

    int buf = 0;
    for (int jb = jb_lo; jb <= jb_hi; jb++) {
        const int s0 = jb * 64;
        CP_WAIT0();
        __syncthreads();

        if (jb + 1 <= jb_hi) {
            const int sn = (jb + 1) * 64;
            const uint32_t kvb = kv_s0 + (uint32_t)((buf ^ 1) * KV_WORDS) * 4;
            #pragma unroll
            for (int i = 0; i < 4; i++) {
                int idx = tid + i * 256;
                int r = idx >> 4, c4 = (idx & 15) * 4;
                cpasync16(kvb + (uint32_t)(r * QSTR + c4) * 4,
                          Kg + (size_t)(sn + r) * 64 + c4);
                cpasync16(kvb + (uint32_t)(64 * QSTR + r * VSTR + c4) * 4,
                          Vg + (size_t)(sn + r) * 64 + c4);
            }
            CP_COMMIT();
        }

        const uint32_t* Ks = KV0 + buf * KV_WORDS;
        const uint32_t* Vs = Ks + 64 * QSTR;

        // ---- S = Q K^T : LDS.64 fragments (pair-permuted d) ----
        float s[8][4];
        #pragma unroll
        for (int nt = 0; nt < 8; nt++)
            #pragma unroll
            for (int l = 0; l < 4; l++) s[nt][l] = 0.f;
        #pragma unroll
        for (int ks = 0; ks < 8; ks++) {
            const int kb = ks * 8;
            uint32_t a[4];
            {
                uint2 lo = *(const uint2*)&Qs[(r0 + g    ) * QSTR + kb + 2 * t];
                uint2 hi = *(const uint2*)&Qs[(r0 + g + 8) * QSTR + kb + 2 * t];
                a[0] = lo.x; a[1] = hi.x; a[2] = lo.y; a[3] = hi.y;
            }
            #pragma unroll
            for (int nt = 0; nt < 8; nt++) {
                uint2 bb = *(const uint2*)&Ks[(nt * 8 + g) * QSTR + kb + 2 * t];
                uint32_t b[2] = {bb.x, bb.y};
                mma_tf32_16n8k8(s[nt], a, b);
            }
        }

        // ---- window mask (s already in log2 scale) ----
        float tm0 = -1e30f, tm1 = -1e30f;
        #pragma unroll
        for (int nt = 0; nt < 8; nt++) {
            int cg = s0 + nt * 8 + 2 * t;
            int d00 = rg0 - cg, d01 = d00 - 1;
            int d10 = rg1 - cg, d11 = d10 - 1;
            s[nt][0] = (d00 >= 0 && d00 < WIN) ? s[nt][0] : -1e30f;
            s[nt][1] = (d01 >= 0 && d01 < WIN) ? s[nt][1] : -1e30f;
            s[nt][2] = (d10 >= 0 && d10 < WIN) ? s[nt][2] : -1e30f;
            s[nt][3] = (d11 >= 0 && d11 < WIN) ? s[nt][3] : -1e30f;
            tm0 = fmaxf(tm0, fmaxf(s[nt][0], s[nt][1]));
            tm1 = fmaxf(tm1, fmaxf(s[nt][2], s[nt][3]));
        }
        tm0 = fmaxf(tm0, __shfl_xor_sync(0xffffffffu, tm0, 1));
        tm0 = fmaxf(tm0, __shfl_xor_sync(0xffffffffu, tm0, 2));
        tm1 = fmaxf(tm1, __shfl_xor_sync(0xffffffffu, tm1, 1));
        tm1 = fmaxf(tm1, __shfl_xor_sync(0xffffffffu, tm1, 2));

        float mn0 = fmaxf(mi0, tm0), mn1 = fmaxf(mi1, tm1);
        float al0 = exp2f(mi0 - mn0), al1 = exp2f(mi1 - mn1);
        mi0 = mn0; mi1 = mn1;
        float rs0 = 0.f, rs1 = 0.f;
        #pragma unroll
        for (int nt = 0; nt < 8; nt++) {
            float p00 = exp2f(s[nt][0] - mn0);
            float p01 = exp2f(s[nt][1] - mn0);
            float p10 = exp2f(s[nt][2] - mn1);
            float p11 = exp2f(s[nt][3] - mn1);
            rs0 += p00 + p01;
            rs1 += p10 + p11;
            int col = nt * 8 + 2 * t;
            *(uint2*)&Ps[(r0 + g    ) * QSTR + col] = make_uint2(f2tf(p00), f2tf(p01));
            *(uint2*)&Ps[(r0 + g + 8) * QSTR + col] = make_uint2(f2tf(p10), f2tf(p11));
            o[nt][0] *= al0; o[nt][1] *= al0;
            o[nt][2] *= al1; o[nt][3] *= al1;
        }
        rs0 += __shfl_xor_sync(0xffffffffu, rs0, 1);
        rs0 += __shfl_xor_sync(0xffffffffu, rs0, 2);
        rs1 += __shfl_xor_sync(0xffffffffu, rs1, 1);
        rs1 += __shfl_xor_sync(0xffffffffu, rs1, 2);
        li0 = li0 * al0 + rs0;
        li1 = li1 * al1 + rs1;
        __syncwarp();

        // ---- O += P V (P logical, V logical transposed-read) ----
        #pragma unroll
        for (int ks = 0; ks < 8; ks++) {
            const int kb = ks * 8;
            uint32_t a[4];
            a[0] = Ps[(r0 + g    ) * QSTR + kb + t];
            a[1] = Ps[(r0 + g + 8) * QSTR + kb + t];
            a[2] = Ps[(r0 + g    ) * QSTR + kb + t + 4];
            a[3] = Ps[(r0 + g + 8) * QSTR + kb + t + 4];
            #pragma unroll
            for (int nt = 0; nt < 8; nt++) {
                uint32_t b[2];
                b[0] = Vs[(kb + t    ) * VSTR + nt * 8 + g];
                b[1] = Vs[(kb + t + 4) * VSTR + nt * 8 + g];
                mma_tf32_16n8k8(o[nt], a, b);
            }
        }
        buf ^= 1;
    }

    // epilogue: normalize; store pair-permuted tf32 for the O-proj GEMM.
    float inv0 = 1.f / li0, inv1 = 1.f / li1;
    const int sb_off = (t < 2) ? 4 * t : 4 * t - 7;
    #pragma unroll
    for (int nt = 0; nt < 8; nt++) {
        int sb = h * 64 + nt * 8 + sb_off;
        g_att[(size_t)rg0 * CC + sb]     = f2tf(o[nt][0] * inv0);
        g_att[(size_t)rg0 * CC + sb + 2] = f2tf(o[nt][1] * inv0);
        g_att[(size_t)rg1 * CC + sb]     = f2tf(o[nt][2] * inv1);
        g_att[(size_t)rg1 * CC + sb + 2] = f2tf(o[nt][3] * inv1);
    }
}

// ---------------------------------------------------------------------------
extern "C" void kernel_launch(void* const* d_in, const int* in_sizes, int n_in,
                              void* d_out, int out_size)
{
    const float* x    = (const float*)d_in[0];
    const float* wqkv = (const float*)d_in[3];
    const float* wo   = (const float*)d_in[4];
    const float* qnw  = (const float*)d_in[5];
    const float* knw  = (const float*)d_in[6];
    const float* cosT = (const float*)d_in[7];
    const float* sinT = (const float*)d_in[8];
    float* out = (float*)d_out;

    float* p_qkv = nullptr;
    uint32_t *p_xt = nullptr, *p_wqkvt = nullptr, *p_wot = nullptr, *p_att = nullptr;
    cudaGetSymbolAddress((void**)&p_qkv, g_qkv);
    cudaGetSymbolAddress((void**)&p_xt, g_xt);
    cudaGetSymbolAddress((void**)&p_wqkvt, g_wqkvt);
    cudaGetSymbolAddress((void**)&p_wot, g_wot);
    cudaGetSymbolAddress((void**)&p_att, g_att);

    // 0) pre-convert fp32 -> tf32 (RN), pair-permuted 8-blocks
    cvt_tf32_perm<<<(TT * CC / 4 + 255) / 256, 256>>>((const float4*)x, p_xt, TT * CC / 4);
    cvt_tf32_perm<<<(3 * CC * CC / 4 + 255) / 256, 256>>>((const float4*)wqkv, p_wqkvt, 3 * CC * CC / 4);
    cvt_tf32_perm<<<(CC * CC / 4 + 255) / 256, 256>>>((const float4*)wo, p_wot, CC * CC / 4);

    cudaFuncSetAttribute(gemm_mma, cudaFuncAttributeMaxDynamicSharedMemorySize, GSMEM_B);
    cudaFuncSetAttribute(attn_mma, cudaFuncAttributeMaxDynamicSharedMemorySize, ATT_SMEM);

    // 1) qkv = x @ w_qkv^T
    gemm_mma<<<dim3(3072 / 128, 4096 / 128), 256, GSMEM_B>>>(p_xt, p_wqkvt, p_qkv, TT, 3 * CC, CC);

    // 2) rmsnorm + rope (+ scale*log2e on Q) -> tf32 [H][T][64]
    qkv_post<<<TT, 512>>>(cosT, sinT, qnw, knw);

    // 3) sliding-window attention -> tf32 att (pair-permuted)
    attn_mma<<<dim3(TT / 128, HH), 256, ATT_SMEM>>>();

    // 4) out = att @ w_o^T
    gemm_mma<<<dim3(1024 / 128, 4096 / 128), 256, GSMEM_B>>>(p_att, p_wot, out, TT, CC, CC);
}